// round 14
// baseline (speedup 1.0000x reference)
#include <cuda_runtime.h>
#include <cuda_bf16.h>
#include <cuda_fp16.h>
#include <math.h>
#include <stdint.h>

// Problem constants (fixed by the dataset)
#define B  16
#define N  1024
#define D  64
#define C  64
#define KMAX 20
#define CAND 32

__device__ __forceinline__ uint32_t smem_to_u32(const void* p) {
    uint32_t a;
    asm("{ .reg .u64 t; cvta.to.shared.u64 t, %1; cvt.u32.u64 %0, t; }"
        : "=r"(a) : "l"(p));
    return a;
}

__device__ __forceinline__ uint32_t redux_min_u32(uint32_t v) {
    uint32_t r;
    asm("redux.sync.min.u32 %0, %1, 0xffffffff;" : "=r"(r) : "r"(v));
    return r;
}

// ---------------------------------------------------------------------------
// Scratch (device globals: no allocation allowed)
// ---------------------------------------------------------------------------
__device__ __half g_dist[B * N * N];                      // approx dist^2, fp16 (32MB)
__device__ __align__(16) __nv_bfloat16 g_xbf[B * N * D];  // bf16 copy of x
__device__ float g_tu[B * N * 2 * C];                     // per-point t | u
__device__ int   g_idx[B * N * KMAX];
__device__ float g_x2[B * N];
__device__ int   g_cnt[B];
__device__ int   g_keff[B];

// ---------------------------------------------------------------------------
// 1) counts + k_eff (mask dtype auto-detect: int32 vs uint8)
// ---------------------------------------------------------------------------
__global__ void k_counts(const void* __restrict__ mask_raw) {
    const unsigned int* mw = (const unsigned int*)mask_raw;
    const bool is_i32 = (mw[0] == 1u);
    int b = threadIdx.x >> 5;
    int lane = threadIdx.x & 31;
    int cnt = 0;
    if (is_i32) {
        const int* mi = (const int*)mask_raw;
        for (int i = lane; i < N; i += 32) cnt += (mi[b * N + i] != 0);
    } else {
        const unsigned char* mb = (const unsigned char*)mask_raw;
        for (int i = lane; i < N; i += 32) cnt += (mb[b * N + i] != 0);
    }
    for (int o = 16; o; o >>= 1) cnt += __shfl_xor_sync(0xffffffffu, cnt, o);
    __shared__ int sc[B];
    if (lane == 0) sc[b] = cnt;
    __syncthreads();
    if (threadIdx.x == 0) {
        int mn = 0x7fffffff;
        for (int i = 0; i < B; i++) mn = min(mn, sc[i]);
        int kg = min(KMAX, max(1, mn - 1));
        for (int i = 0; i < B; i++) {
            g_cnt[i] = sc[i];
            float v = sqrtf((float)sc[i] / 50.0f) * 8.0f;
            v = fminf(fmaxf(v, 8.0f), 20.0f);
            int kp = (int)v;
            g_keff[i] = min(kp, kg);
        }
    }
}

// ---------------------------------------------------------------------------
// 2) squared norms + bf16 conversion of x
// ---------------------------------------------------------------------------
__global__ void k_x2(const float* __restrict__ x) {
    int p = blockIdx.x * 256 + threadIdx.x;     // 0..B*N-1
    const float4* xp = reinterpret_cast<const float4*>(x + (size_t)p * D);
    __nv_bfloat162* bp = reinterpret_cast<__nv_bfloat162*>(g_xbf + (size_t)p * D);
    float s = 0.f;
#pragma unroll
    for (int i = 0; i < D / 4; i++) {
        float4 v = xp[i];
        s += v.x * v.x + v.y * v.y + v.z * v.z + v.w * v.w;
        bp[2 * i + 0] = __floats2bfloat162_rn(v.x, v.y);
        bp[2 * i + 1] = __floats2bfloat162_rn(v.z, v.w);
    }
    g_x2[p] = s;
}

// ---------------------------------------------------------------------------
// 3) dist^2 via mma.sync bf16: per CTA a 128x128 tile of one batch.
//    Validity-aware: rowBase>=cnt -> CTA exit; colBase>=cnt -> INF pattern.
// ---------------------------------------------------------------------------
#define AS_STRIDE 72

__global__ void __launch_bounds__(256) k_dist_mma() {
    __shared__ __align__(16) __nv_bfloat16 As[128 * AS_STRIDE];
    __shared__ __align__(16) __nv_bfloat16 Bs[128 * AS_STRIDE];
    __shared__ float s_x2r[128], s_x2c[128];

    const int tid = threadIdx.x;
    const int wid = tid >> 5;
    const int lane = tid & 31;
    const int b = blockIdx.z;
    const int rowBase = blockIdx.y << 7;
    const int colBase = blockIdx.x << 7;
    const int cnt = g_cnt[b];

    if (rowBase >= cnt) return;            // rows never read downstream
    if (colBase >= cnt) {                  // all-INF tile: store pattern only
        const uint4 iv = make_uint4(0x7C007C00u, 0x7C007C00u,
                                    0x7C007C00u, 0x7C007C00u);
#pragma unroll
        for (int i = 0; i < 8; i++) {
            int idx = tid * 8 + i;         // 0..2047 = 128 rows x 16 uint4
            int r = idx >> 4, q = idx & 15;
            *(uint4*)&g_dist[(((size_t)(b << 10) + rowBase + r) << 10)
                             + colBase + q * 8] = iv;
        }
        return;
    }

    const uint4* gA = (const uint4*)(g_xbf + (((size_t)(b << 10) + rowBase) << 6));
    const uint4* gB = (const uint4*)(g_xbf + (((size_t)(b << 10) + colBase) << 6));
#pragma unroll
    for (int i = 0; i < 4; i++) {
        int idx = tid + i * 256;                 // 0..1023 = 128 rows x 8 uint4
        int r = idx >> 3, q = idx & 7;
        *(uint4*)&As[r * AS_STRIDE + q * 8] = gA[idx];
        *(uint4*)&Bs[r * AS_STRIDE + q * 8] = gB[idx];
    }
    if (tid < 128) {
        s_x2r[tid] = g_x2[(b << 10) + rowBase + tid];
        s_x2c[tid] = g_x2[(b << 10) + colBase + tid];
    }
    __syncthreads();

    const int wr = wid >> 2;            // 0..1  (m block of 64)
    const int wc = wid & 3;             // 0..3  (n block of 32)
    const int m0 = wr * 64;
    const int n0 = wc * 32;

    float c[4][4][4];
#pragma unroll
    for (int mi = 0; mi < 4; mi++)
#pragma unroll
        for (int ni = 0; ni < 4; ni++)
#pragma unroll
            for (int e = 0; e < 4; e++) c[mi][ni][e] = 0.f;

#pragma unroll
    for (int ks = 0; ks < 4; ks++) {
        const int kb = ks * 16;
        uint32_t a[4][4];
#pragma unroll
        for (int mi = 0; mi < 4; mi++) {
            uint32_t addr = smem_to_u32(
                &As[(m0 + mi * 16 + (lane & 15)) * AS_STRIDE + kb + ((lane >> 4) << 3)]);
            asm volatile(
                "ldmatrix.sync.aligned.m8n8.x4.shared.b16 {%0,%1,%2,%3}, [%4];"
                : "=r"(a[mi][0]), "=r"(a[mi][1]), "=r"(a[mi][2]), "=r"(a[mi][3])
                : "r"(addr));
        }
        uint32_t bf[4][2];
#pragma unroll
        for (int ni = 0; ni < 4; ni++) {
            uint32_t addr = smem_to_u32(
                &Bs[(n0 + ni * 8 + (lane & 7)) * AS_STRIDE + kb + (lane & 8)]);
            asm volatile(
                "ldmatrix.sync.aligned.m8n8.x2.shared.b16 {%0,%1}, [%2];"
                : "=r"(bf[ni][0]), "=r"(bf[ni][1])
                : "r"(addr));
        }
#pragma unroll
        for (int mi = 0; mi < 4; mi++)
#pragma unroll
            for (int ni = 0; ni < 4; ni++)
                asm volatile(
                    "mma.sync.aligned.m16n8k16.row.col.f32.bf16.bf16.f32 "
                    "{%0,%1,%2,%3}, {%4,%5,%6,%7}, {%8,%9}, {%0,%1,%2,%3};"
                    : "+f"(c[mi][ni][0]), "+f"(c[mi][ni][1]),
                      "+f"(c[mi][ni][2]), "+f"(c[mi][ni][3])
                    : "r"(a[mi][0]), "r"(a[mi][1]), "r"(a[mi][2]), "r"(a[mi][3]),
                      "r"(bf[ni][0]), "r"(bf[ni][1]));
    }

    // epilogue (fp16 store)
    const int groupID = lane >> 2;
    const int tig = lane & 3;
#pragma unroll
    for (int mi = 0; mi < 4; mi++) {
#pragma unroll
        for (int half = 0; half < 2; half++) {
            const int lr = m0 + mi * 16 + groupID + half * 8;   // local row
            const int gi = rowBase + lr;
            const float x2i = s_x2r[lr];
            const bool rowv = gi < cnt;
#pragma unroll
            for (int ni = 0; ni < 4; ni++) {
                const int lc = n0 + ni * 8 + tig * 2;           // local col
                const int gm = colBase + lc;
                float d0 = fmaf(-2.0f, c[mi][ni][half * 2 + 0], x2i + s_x2c[lc]);
                float d1 = fmaf(-2.0f, c[mi][ni][half * 2 + 1], x2i + s_x2c[lc + 1]);
                d0 = fmaxf(d0, 0.0f);
                d1 = fmaxf(d1, 0.0f);
                if (gi == gm     || !rowv || gm     >= cnt) d0 = INFINITY;
                if (gi == gm + 1 || !rowv || gm + 1 >= cnt) d1 = INFINITY;
                *(__half2*)&g_dist[(((size_t)(b << 10) + gi) << 10) + gm] =
                    __floats2half2_rn(d0, d1);
            }
        }
    }
}

// ---------------------------------------------------------------------------
// 4) selection: ONE WARP PER ROW, packed-key top-k with redux.sync pops.
//    Key = (fp16_bits << 16) | gcol — uint order == (value, index) order.
// ---------------------------------------------------------------------------
#define INF_KEY 0xFFFFFFFFu

__global__ void __launch_bounds__(128) k_select(const float* __restrict__ x) {
    const int warp = (blockIdx.x << 2) + (threadIdx.x >> 5);   // row id
    const int lane = threadIdx.x & 31;
    const int w = threadIdx.x >> 5;
    __shared__ __align__(16) float sxi[4][64];
    __shared__ int   scand[4][32];
    __shared__ float sdot[4][32];
    const int b = warp >> 10;
    const int n = warp & 1023;
    if (n >= g_cnt[b]) return;             // warp-uniform

    const __half* drow = &g_dist[(size_t)warp << 10];
    uint32_t pk[16];                       // 32 halfs packed 2/reg
#pragma unroll
    for (int q = 0; q < 4; q++) {
        uint4 t = *reinterpret_cast<const uint4*>(drow + q * 256 + lane * 8);
        pk[q * 4 + 0] = t.x; pk[q * 4 + 1] = t.y;
        pk[q * 4 + 2] = t.z; pk[q * 4 + 3] = t.w;
    }
    const uint32_t lb = lane << 3;         // lane's column base

    // build per-lane sorted top-4 keys (ascending)
    uint32_t t0 = INF_KEY, t1 = INF_KEY, t2 = INF_KEY, t3 = INF_KEY;
#pragma unroll
    for (int r = 0; r < 16; r++) {
        const uint32_t cbase = lb + ((r >> 2) << 8) + ((r & 3) << 1);
        uint32_t klo = (pk[r] << 16) | cbase;
        uint32_t khi = (pk[r] & 0xFFFF0000u) | (cbase + 1);
#pragma unroll
        for (int h = 0; h < 2; h++) {
            uint32_t k = h ? khi : klo;
            if (k < t3) {
                bool b0 = k < t0, b1 = k < t1, b2 = k < t2;
                t3 = b2 ? t2 : k;
                t2 = b2 ? (b1 ? t1 : k) : t2;
                t1 = b1 ? (b0 ? t0 : k) : t1;
                t0 = b0 ? k : t0;
            }
        }
    }
    int      occ = 4;
    uint32_t lastk = 0;
    uint32_t mycand = 0;

    for (int it = 0; it < CAND; it++) {
        const uint32_t rv = redux_min_u32(t0);
        if (it == lane) mycand = rv & 0x3FFu;
        if (lane == (int)((rv >> 3) & 31)) {   // owning lane from col bits
            lastk = t0;
            t0 = t1; t1 = t2; t2 = t3; t3 = INF_KEY;
            if (--occ == 0) {
                // rare exact refill: next 4 keys strictly greater than lastk
                t0 = t1 = t2 = t3 = INF_KEY;
#pragma unroll
                for (int r = 0; r < 16; r++) {
                    const uint32_t cbase = lb + ((r >> 2) << 8) + ((r & 3) << 1);
                    uint32_t klo = (pk[r] << 16) | cbase;
                    uint32_t khi = (pk[r] & 0xFFFF0000u) | (cbase + 1);
#pragma unroll
                    for (int h = 0; h < 2; h++) {
                        uint32_t k = h ? khi : klo;
                        if (k > lastk && k < t3) {
                            bool b0 = k < t0, b1 = k < t1, b2 = k < t2;
                            t3 = b2 ? t2 : k;
                            t2 = b2 ? (b1 ? t1 : k) : t2;
                            t1 = b1 ? (b0 ? t0 : k) : t1;
                            t0 = b0 ? k : t0;
                        }
                    }
                }
                occ = 4;
            }
        }
    }

    // ---- coalesced exact fp32 rescore: 4 lanes per candidate, 8 cands/rep ----
    const float* xb = x + (((size_t)(b << 10)) << 6);
    const float2* xip = (const float2*)(xb + ((size_t)n << 6));
    float2 xi2 = xip[lane];
    *(float2*)&sxi[w][lane * 2] = xi2;
    scand[w][lane] = (int)mycand;
    __syncwarp();
    const float4* xs4 = (const float4*)sxi[w];
    const int sub = lane & 3;          // position within quad
#pragma unroll
    for (int rep = 0; rep < 4; rep++) {
        const int ci = rep * 8 + (lane >> 2);
        const int cq = scand[w][ci];
        const float4* xc = (const float4*)(xb + ((size_t)cq << 6));
        float part = 0.f;
#pragma unroll
        for (int q = 0; q < 4; q++) {
            float4 cv = xc[q * 4 + sub];       // contiguous 64B per quad
            float4 xq = xs4[q * 4 + sub];
            part = fmaf(cv.x, xq.x, part);
            part = fmaf(cv.y, xq.y, part);
            part = fmaf(cv.z, xq.z, part);
            part = fmaf(cv.w, xq.w, part);
        }
        part += __shfl_xor_sync(0xffffffffu, part, 1);
        part += __shfl_xor_sync(0xffffffffu, part, 2);
        if (sub == 0) sdot[w][ci] = part;
    }
    __syncwarp();
    const int myc = scand[w][lane];
    float dv = fmaxf(fmaf(-2.0f, sdot[w][lane],
                          g_x2[(b << 10) + n] + g_x2[(b << 10) + myc]), 0.0f);
    int ci = myc;

    // ---- bitonic sort 32 lanes by (value, index) ascending ----
#pragma unroll
    for (int k = 2; k <= 32; k <<= 1) {
#pragma unroll
        for (int j = k >> 1; j > 0; j >>= 1) {
            float ov = __shfl_xor_sync(0xffffffffu, dv, j);
            int   oi = __shfl_xor_sync(0xffffffffu, ci, j);
            bool up = ((lane & k) == 0);
            bool lower = ((lane & j) == 0);
            bool otherLess = (ov < dv) || (ov == dv && oi < ci);
            bool take = (up == lower) ? otherLess : !otherLess;
            if (take) { dv = ov; ci = oi; }
        }
    }
    if (lane < KMAX) {
        int ke = g_keff[b];
        g_idx[warp * KMAX + lane] = (lane < ke) ? ci : 0;   // pad = first valid (0)
    }
}

// ---------------------------------------------------------------------------
// 5) per-point t = x@(W1a - W1b) + b1  and  u = x@W1b.  32 rows per block.
//    Blocks whose rows are all invalid exit (rows never read downstream).
// ---------------------------------------------------------------------------
__global__ void k_tu(const float* __restrict__ x, const float* __restrict__ W1,
                     const float* __restrict__ b1) {
    __shared__ float xs[32][64];
    __shared__ __align__(16) float w1s[64][128];
    const int tid = threadIdx.x;            // 256
    const int rowBase = blockIdx.x * 32;
    if ((rowBase & 1023) >= g_cnt[rowBase >> 10]) return;   // block-uniform

    for (int idx = tid; idx < 64 * 128; idx += 256) {
        int d = idx >> 7, c = idx & 127;
        float v;
        if (c < 64) v = W1[d * 64 + c] - W1[(64 + d) * 64 + c];
        else        v = W1[(64 + d) * 64 + (c - 64)];
        w1s[d][c] = v;
    }
    for (int idx = tid; idx < 32 * 64; idx += 256) {
        int r = idx >> 6, k = idx & 63;
        xs[r][k] = x[(size_t)(rowBase + r) * D + k];
    }
    __syncthreads();

    const int tx = tid & 15;
    const int ty = tid >> 4;
    float acc[2][8] = {};
    for (int k = 0; k < 64; k++) {
        float a0 = xs[ty * 2 + 0][k];
        float a1 = xs[ty * 2 + 1][k];
        float4 w0 = *reinterpret_cast<const float4*>(&w1s[k][tx * 8 + 0]);
        float4 w1v = *reinterpret_cast<const float4*>(&w1s[k][tx * 8 + 4]);
        float w[8] = {w0.x, w0.y, w0.z, w0.w, w1v.x, w1v.y, w1v.z, w1v.w};
#pragma unroll
        for (int j = 0; j < 8; j++) {
            acc[0][j] = fmaf(a0, w[j], acc[0][j]);
            acc[1][j] = fmaf(a1, w[j], acc[1][j]);
        }
    }
#pragma unroll
    for (int i = 0; i < 2; i++) {
        int row = rowBase + ty * 2 + i;
#pragma unroll
        for (int j = 0; j < 8; j++) {
            int c = tx * 8 + j;
            float v = acc[i][j] + (c < 64 ? b1[c] : 0.0f);
            g_tu[(size_t)row * 128 + c] = v;
        }
    }
}

// ---------------------------------------------------------------------------
// 6) fused via tf32 mma: 16 rows per CTA, each warp loops over 4 rows —
//    amortizes the W2 smem tile load 4x. Per row: phase 1 gather u,
//    GroupNorm+ReLU, cvt tf32 -> smem h[24x64]; phase 2 m16n8k8 tf32 GEMM
//    out[64 ch][24 edges], max over valid edge cols, +b2, store.
// ---------------------------------------------------------------------------
#define HS_STRIDE 68
#define W2_STRIDE 72
#define FUSED_ROWS 16

__device__ __forceinline__ void mma_tf32(float* c, uint32_t a0, uint32_t a1,
                                         uint32_t a2, uint32_t a3,
                                         uint32_t b0v, uint32_t b1v) {
    asm volatile(
        "mma.sync.aligned.m16n8k8.row.col.f32.tf32.tf32.f32 "
        "{%0,%1,%2,%3}, {%4,%5,%6,%7}, {%8,%9}, {%0,%1,%2,%3};"
        : "+f"(c[0]), "+f"(c[1]), "+f"(c[2]), "+f"(c[3])
        : "r"(a0), "r"(a1), "r"(a2), "r"(a3), "r"(b0v), "r"(b1v));
}

__global__ void __launch_bounds__(128) k_fused_mma(
    const float* __restrict__ W2, const float* __restrict__ b2,
    const float* __restrict__ gamma, const float* __restrict__ beta,
    float* __restrict__ out) {
    __shared__ float W2s[64 * W2_STRIDE];      // A[m][k]=W2[k][m], stored [k][m]
    __shared__ float hs[4][24 * HS_STRIDE];    // per-warp h tile [edge][ch]

    const int tid = threadIdx.x;
    const int w = tid >> 5;
    const int lane = tid & 31;
    const int gID = lane >> 2;
    const int tig = lane & 3;
    const unsigned FULL = 0xffffffffu;

    // load W2 into smem as tf32 bits (once per CTA, serves 16 rows)
    for (int idx = tid; idx < 64 * 64; idx += 128) {
        int k = idx >> 6, m = idx & 63;
        uint32_t tv;
        asm("cvt.rna.tf32.f32 %0, %1;" : "=r"(tv) : "f"(W2[idx]));
        W2s[k * W2_STRIDE + m] = __uint_as_float(tv);
    }
    __syncthreads();

    const int rowBase = blockIdx.x * FUSED_ROWS;   // 16 rows, one batch
    const int b = rowBase >> 10;
    const int cnt = g_cnt[b];
    float* hw = hs[w];

    // static zero pad rows (only phase-1 rows 0..19 are rewritten per row)
#pragma unroll
    for (int j = KMAX; j < 24; j++)
        *(float2*)&hw[j * HS_STRIDE + 2 * lane] = make_float2(0.f, 0.f);

    const float2 gm = *(const float2*)&gamma[2 * lane];
    const float2 bt = *(const float2*)&beta[2 * lane];

    for (int rr = 0; rr < FUSED_ROWS / 4; rr++) {
        const int row = rowBase + w * (FUSED_ROWS / 4) + rr;
        const int n = row & 1023;

        if (n >= cnt) {
            *(float2*)&out[(size_t)row * 64 + 2 * lane] = make_float2(0.f, 0.f);
            continue;
        }

        // ---- phase 1: h = relu(groupnorm(t + u_j)) -> smem tf32 ----
        int myidx = (lane < KMAX) ? g_idx[row * KMAX + lane] : 0;
        const float2 t2 = *(const float2*)&g_tu[(size_t)row * 128 + 2 * lane];
#pragma unroll 4
        for (int j = 0; j < KMAX; j++) {
            int sid = __shfl_sync(FULL, myidx, j);
            const float2 u2 = *(const float2*)
                &g_tu[((size_t)((b << 10) + sid)) * 128 + 64 + 2 * lane];
            float h0 = t2.x + u2.x, h1 = t2.y + u2.y;
            float s = h0 + h1;
            s += __shfl_xor_sync(FULL, s, 1);
            const float mu = s * 0.25f;
            const float d0 = h0 - mu, d1 = h1 - mu;
            float vv = d0 * d0 + d1 * d1;
            vv += __shfl_xor_sync(FULL, vv, 1);
            const float rstd = rsqrtf(vv * 0.25f + 1e-5f);
            float hn0 = fmaxf(fmaf(d0 * rstd, gm.x, bt.x), 0.f);
            float hn1 = fmaxf(fmaf(d1 * rstd, gm.y, bt.y), 0.f);
            uint32_t p0, p1;
            asm("cvt.rna.tf32.f32 %0, %1;" : "=r"(p0) : "f"(hn0));
            asm("cvt.rna.tf32.f32 %0, %1;" : "=r"(p1) : "f"(hn1));
            hw[j * HS_STRIDE + 2 * lane]     = __uint_as_float(p0);
            hw[j * HS_STRIDE + 2 * lane + 1] = __uint_as_float(p1);
        }
        __syncwarp();

        // ---- phase 2: GEMM M=64 (out_ch), N=24 (edges), K=64 (in_ch) ----
        float c[4][3][4];
#pragma unroll
        for (int mt = 0; mt < 4; mt++)
#pragma unroll
            for (int nt = 0; nt < 3; nt++)
#pragma unroll
                for (int e = 0; e < 4; e++) c[mt][nt][e] = 0.f;

#pragma unroll
        for (int k0 = 0; k0 < 8; k0++) {
            const int kk = k0 * 8;
            uint32_t bf[3][2];
#pragma unroll
            for (int nt = 0; nt < 3; nt++) {
                bf[nt][0] = __float_as_uint(hw[(nt * 8 + gID) * HS_STRIDE + kk + tig]);
                bf[nt][1] = __float_as_uint(hw[(nt * 8 + gID) * HS_STRIDE + kk + tig + 4]);
            }
#pragma unroll
            for (int mt = 0; mt < 4; mt++) {
                const int mb = mt * 16 + gID;
                uint32_t a0 = __float_as_uint(W2s[(kk + tig) * W2_STRIDE + mb]);
                uint32_t a1 = __float_as_uint(W2s[(kk + tig) * W2_STRIDE + mb + 8]);
                uint32_t a2 = __float_as_uint(W2s[(kk + tig + 4) * W2_STRIDE + mb]);
                uint32_t a3 = __float_as_uint(W2s[(kk + tig + 4) * W2_STRIDE + mb + 8]);
#pragma unroll
                for (int nt = 0; nt < 3; nt++)
                    mma_tf32(c[mt][nt], a0, a1, a2, a3, bf[nt][0], bf[nt][1]);
            }
        }
        __syncwarp();   // all lanes done reading hw before next row rewrites it

        // ---- epilogue: max over edge columns (exclude pad cols >= 20) ----
        const bool inc2 = (tig < 2);   // ntile 2 cols 16+2tig(,+1) < 20
#pragma unroll
        for (int mt = 0; mt < 4; mt++) {
            float m0v = fmaxf(fmaxf(c[mt][0][0], c[mt][0][1]),
                              fmaxf(c[mt][1][0], c[mt][1][1]));
            float m1v = fmaxf(fmaxf(c[mt][0][2], c[mt][0][3]),
                              fmaxf(c[mt][1][2], c[mt][1][3]));
            if (inc2) {
                m0v = fmaxf(m0v, fmaxf(c[mt][2][0], c[mt][2][1]));
                m1v = fmaxf(m1v, fmaxf(c[mt][2][2], c[mt][2][3]));
            }
            m0v = fmaxf(m0v, __shfl_xor_sync(FULL, m0v, 1));
            m0v = fmaxf(m0v, __shfl_xor_sync(FULL, m0v, 2));
            m1v = fmaxf(m1v, __shfl_xor_sync(FULL, m1v, 1));
            m1v = fmaxf(m1v, __shfl_xor_sync(FULL, m1v, 2));
            if (tig == 0) {
                const int ch0 = mt * 16 + gID;
                out[(size_t)row * 64 + ch0]     = m0v + b2[ch0];
                out[(size_t)row * 64 + ch0 + 8] = m1v + b2[ch0 + 8];
            }
        }
    }
}

// ---------------------------------------------------------------------------
// launch
// ---------------------------------------------------------------------------
extern "C" void kernel_launch(void* const* d_in, const int* in_sizes, int n_in,
                              void* d_out, int out_size) {
    const float* x = (const float*)d_in[0];
    const void* mask = d_in[1];
    const float* W1 = (const float*)d_in[2];
    const float* b1 = (const float*)d_in[3];
    const float* gamma = (const float*)d_in[4];
    const float* beta = (const float*)d_in[5];
    const float* W2 = (const float*)d_in[6];
    const float* b2 = (const float*)d_in[7];
    float* out = (float*)d_out;

    k_counts<<<1, 512>>>(mask);
    k_x2<<<(B * N) / 256, 256>>>(x);
    k_dist_mma<<<dim3(N / 128, N / 128, B), 256>>>();
    k_select<<<(B * N) / 4, 128>>>(x);
    k_tu<<<(B * N) / 32, 256>>>(x, W1, b1);
    k_fused_mma<<<(B * N) / FUSED_ROWS, 128>>>(W2, b2, gamma, beta, out);
}

// round 16
// speedup vs baseline: 1.0734x; 1.0734x over previous
#include <cuda_runtime.h>
#include <cuda_bf16.h>
#include <cuda_fp16.h>
#include <math.h>
#include <stdint.h>

// Problem constants (fixed by the dataset)
#define B  16
#define N  1024
#define D  64
#define C  64
#define KMAX 20
#define CAND 32

__device__ __forceinline__ uint32_t smem_to_u32(const void* p) {
    uint32_t a;
    asm("{ .reg .u64 t; cvta.to.shared.u64 t, %1; cvt.u32.u64 %0, t; }"
        : "=r"(a) : "l"(p));
    return a;
}

__device__ __forceinline__ uint32_t redux_min_u32(uint32_t v) {
    uint32_t r;
    asm("redux.sync.min.u32 %0, %1, 0xffffffff;" : "=r"(r) : "r"(v));
    return r;
}

// ---------------------------------------------------------------------------
// Scratch (device globals: no allocation allowed)
// ---------------------------------------------------------------------------
__device__ __half g_dist[B * N * N];                      // approx dist^2, fp16 (32MB)
__device__ __align__(16) __nv_bfloat16 g_xbf[B * N * D];  // bf16 copy of x
__device__ float g_tu[B * N * 2 * C];                     // per-point t | u
__device__ int   g_idx[B * N * KMAX];
__device__ float g_x2[B * N];
__device__ int   g_cnt[B];
__device__ int   g_keff[B];

// ---------------------------------------------------------------------------
// 1) fused x2/bf16-convert (blocks 0..63) + counts/k_eff (block 64)
// ---------------------------------------------------------------------------
__global__ void k_x2c(const float* __restrict__ x,
                      const void* __restrict__ mask_raw) {
    if (blockIdx.x < 64) {
        int p = blockIdx.x * 256 + threadIdx.x;     // 0..B*N-1
        const float4* xp = reinterpret_cast<const float4*>(x + (size_t)p * D);
        __nv_bfloat162* bp = reinterpret_cast<__nv_bfloat162*>(g_xbf + (size_t)p * D);
        float s = 0.f;
#pragma unroll
        for (int i = 0; i < D / 4; i++) {
            float4 v = xp[i];
            s += v.x * v.x + v.y * v.y + v.z * v.z + v.w * v.w;
            bp[2 * i + 0] = __floats2bfloat162_rn(v.x, v.y);
            bp[2 * i + 1] = __floats2bfloat162_rn(v.z, v.w);
        }
        g_x2[p] = s;
        return;
    }
    // counts block: 8 warps, each handles 2 batches
    const unsigned int* mw = (const unsigned int*)mask_raw;
    const bool is_i32 = (mw[0] == 1u);
    const int wi = threadIdx.x >> 5;
    const int lane = threadIdx.x & 31;
    __shared__ int sc[B];
    for (int bb = wi; bb < B; bb += 8) {
        int cnt = 0;
        if (is_i32) {
            const int* mi = (const int*)mask_raw;
            for (int i = lane; i < N; i += 32) cnt += (mi[bb * N + i] != 0);
        } else {
            const unsigned char* mb = (const unsigned char*)mask_raw;
            for (int i = lane; i < N; i += 32) cnt += (mb[bb * N + i] != 0);
        }
        for (int o = 16; o; o >>= 1) cnt += __shfl_xor_sync(0xffffffffu, cnt, o);
        if (lane == 0) sc[bb] = cnt;
    }
    __syncthreads();
    if (threadIdx.x == 0) {
        int mn = 0x7fffffff;
        for (int i = 0; i < B; i++) mn = min(mn, sc[i]);
        int kg = min(KMAX, max(1, mn - 1));
        for (int i = 0; i < B; i++) {
            g_cnt[i] = sc[i];
            float v = sqrtf((float)sc[i] / 50.0f) * 8.0f;
            v = fminf(fmaxf(v, 8.0f), 20.0f);
            int kp = (int)v;
            g_keff[i] = min(kp, kg);
        }
    }
}

// ---------------------------------------------------------------------------
// 3) dist^2 via mma.sync bf16: per CTA a 128x128 tile of one batch.
//    rowBase>=cnt or colBase>=cnt -> CTA exit (select masks invalid cols).
// ---------------------------------------------------------------------------
#define AS_STRIDE 72

__global__ void __launch_bounds__(256) k_dist_mma() {
    __shared__ __align__(16) __nv_bfloat16 As[128 * AS_STRIDE];
    __shared__ __align__(16) __nv_bfloat16 Bs[128 * AS_STRIDE];
    __shared__ float s_x2r[128], s_x2c[128];

    const int tid = threadIdx.x;
    const int wid = tid >> 5;
    const int lane = tid & 31;
    const int b = blockIdx.z;
    const int rowBase = blockIdx.y << 7;
    const int colBase = blockIdx.x << 7;
    const int cnt = g_cnt[b];

    if (rowBase >= cnt || colBase >= cnt) return;   // never used downstream

    const uint4* gA = (const uint4*)(g_xbf + (((size_t)(b << 10) + rowBase) << 6));
    const uint4* gB = (const uint4*)(g_xbf + (((size_t)(b << 10) + colBase) << 6));
#pragma unroll
    for (int i = 0; i < 4; i++) {
        int idx = tid + i * 256;                 // 0..1023 = 128 rows x 8 uint4
        int r = idx >> 3, q = idx & 7;
        *(uint4*)&As[r * AS_STRIDE + q * 8] = gA[idx];
        *(uint4*)&Bs[r * AS_STRIDE + q * 8] = gB[idx];
    }
    if (tid < 128) {
        s_x2r[tid] = g_x2[(b << 10) + rowBase + tid];
        s_x2c[tid] = g_x2[(b << 10) + colBase + tid];
    }
    __syncthreads();

    const int wr = wid >> 2;            // 0..1  (m block of 64)
    const int wc = wid & 3;             // 0..3  (n block of 32)
    const int m0 = wr * 64;
    const int n0 = wc * 32;

    float c[4][4][4];
#pragma unroll
    for (int mi = 0; mi < 4; mi++)
#pragma unroll
        for (int ni = 0; ni < 4; ni++)
#pragma unroll
            for (int e = 0; e < 4; e++) c[mi][ni][e] = 0.f;

#pragma unroll
    for (int ks = 0; ks < 4; ks++) {
        const int kb = ks * 16;
        uint32_t a[4][4];
#pragma unroll
        for (int mi = 0; mi < 4; mi++) {
            uint32_t addr = smem_to_u32(
                &As[(m0 + mi * 16 + (lane & 15)) * AS_STRIDE + kb + ((lane >> 4) << 3)]);
            asm volatile(
                "ldmatrix.sync.aligned.m8n8.x4.shared.b16 {%0,%1,%2,%3}, [%4];"
                : "=r"(a[mi][0]), "=r"(a[mi][1]), "=r"(a[mi][2]), "=r"(a[mi][3])
                : "r"(addr));
        }
        uint32_t bf[4][2];
#pragma unroll
        for (int ni = 0; ni < 4; ni++) {
            uint32_t addr = smem_to_u32(
                &Bs[(n0 + ni * 8 + (lane & 7)) * AS_STRIDE + kb + (lane & 8)]);
            asm volatile(
                "ldmatrix.sync.aligned.m8n8.x2.shared.b16 {%0,%1}, [%2];"
                : "=r"(bf[ni][0]), "=r"(bf[ni][1])
                : "r"(addr));
        }
#pragma unroll
        for (int mi = 0; mi < 4; mi++)
#pragma unroll
            for (int ni = 0; ni < 4; ni++)
                asm volatile(
                    "mma.sync.aligned.m16n8k16.row.col.f32.bf16.bf16.f32 "
                    "{%0,%1,%2,%3}, {%4,%5,%6,%7}, {%8,%9}, {%0,%1,%2,%3};"
                    : "+f"(c[mi][ni][0]), "+f"(c[mi][ni][1]),
                      "+f"(c[mi][ni][2]), "+f"(c[mi][ni][3])
                    : "r"(a[mi][0]), "r"(a[mi][1]), "r"(a[mi][2]), "r"(a[mi][3]),
                      "r"(bf[ni][0]), "r"(bf[ni][1]));
    }

    // epilogue (fp16 store)
    const int groupID = lane >> 2;
    const int tig = lane & 3;
#pragma unroll
    for (int mi = 0; mi < 4; mi++) {
#pragma unroll
        for (int half = 0; half < 2; half++) {
            const int lr = m0 + mi * 16 + groupID + half * 8;   // local row
            const int gi = rowBase + lr;
            const float x2i = s_x2r[lr];
            const bool rowv = gi < cnt;
#pragma unroll
            for (int ni = 0; ni < 4; ni++) {
                const int lc = n0 + ni * 8 + tig * 2;           // local col
                const int gm = colBase + lc;
                float d0 = fmaf(-2.0f, c[mi][ni][half * 2 + 0], x2i + s_x2c[lc]);
                float d1 = fmaf(-2.0f, c[mi][ni][half * 2 + 1], x2i + s_x2c[lc + 1]);
                d0 = fmaxf(d0, 0.0f);
                d1 = fmaxf(d1, 0.0f);
                if (gi == gm     || !rowv || gm     >= cnt) d0 = INFINITY;
                if (gi == gm + 1 || !rowv || gm + 1 >= cnt) d1 = INFINITY;
                *(__half2*)&g_dist[(((size_t)(b << 10) + gi) << 10) + gm] =
                    __floats2half2_rn(d0, d1);
            }
        }
    }
}

// ---------------------------------------------------------------------------
// 4) selection: ONE WARP PER ROW, packed-key top-k with redux.sync pops.
//    Key = (fp16_bits << 16) | gcol — uint order == (value, index) order.
//    Cols >= cnt are masked at load (quarter skip + partial-quarter mask),
//    so dist never materializes invalid columns.
// ---------------------------------------------------------------------------
#define INF_KEY 0xFFFFFFFFu

__global__ void __launch_bounds__(128) k_select(const float* __restrict__ x) {
    const int warp = (blockIdx.x << 2) + (threadIdx.x >> 5);   // row id
    const int lane = threadIdx.x & 31;
    const int w = threadIdx.x >> 5;
    __shared__ __align__(16) float sxi[4][64];
    __shared__ int   scand[4][32];
    __shared__ float sdot[4][32];
    const int b = warp >> 10;
    const int n = warp & 1023;
    const int cnt = g_cnt[b];
    if (n >= cnt) return;                  // warp-uniform

    const __half* drow = &g_dist[(size_t)warp << 10];
    uint32_t pk[16];                       // 32 halfs packed 2/reg
#pragma unroll
    for (int q = 0; q < 4; q++) {
        if (q * 256 >= cnt) {              // fully invalid quarter: no load
            pk[q * 4 + 0] = pk[q * 4 + 1] = INF_KEY;
            pk[q * 4 + 2] = pk[q * 4 + 3] = INF_KEY;
            continue;
        }
        uint4 t = *reinterpret_cast<const uint4*>(drow + q * 256 + lane * 8);
        pk[q * 4 + 0] = t.x; pk[q * 4 + 1] = t.y;
        pk[q * 4 + 2] = t.z; pk[q * 4 + 3] = t.w;
        if ((q + 1) * 256 > cnt) {         // partial quarter: mask cols >= cnt
#pragma unroll
            for (int r = 0; r < 4; r++) {
                int col0 = q * 256 + (lane << 3) + r * 2;
                if (col0 >= cnt)     pk[q * 4 + r] |= 0x0000FFFFu;
                if (col0 + 1 >= cnt) pk[q * 4 + r] |= 0xFFFF0000u;
            }
        }
    }
    const uint32_t lb = lane << 3;         // lane's column base

    // build per-lane sorted top-4 keys (ascending)
    uint32_t t0 = INF_KEY, t1 = INF_KEY, t2 = INF_KEY, t3 = INF_KEY;
#pragma unroll
    for (int r = 0; r < 16; r++) {
        const uint32_t cbase = lb + ((r >> 2) << 8) + ((r & 3) << 1);
        uint32_t klo = (pk[r] << 16) | cbase;
        uint32_t khi = (pk[r] & 0xFFFF0000u) | (cbase + 1);
#pragma unroll
        for (int h = 0; h < 2; h++) {
            uint32_t k = h ? khi : klo;
            if (k < t3) {
                bool b0 = k < t0, b1 = k < t1, b2 = k < t2;
                t3 = b2 ? t2 : k;
                t2 = b2 ? (b1 ? t1 : k) : t2;
                t1 = b1 ? (b0 ? t0 : k) : t1;
                t0 = b0 ? k : t0;
            }
        }
    }
    int      occ = 4;
    uint32_t lastk = 0;
    uint32_t mycand = 0;

    for (int it = 0; it < CAND; it++) {
        const uint32_t rv = redux_min_u32(t0);
        if (it == lane) mycand = rv & 0x3FFu;
        if (lane == (int)((rv >> 3) & 31)) {   // owning lane from col bits
            lastk = t0;
            t0 = t1; t1 = t2; t2 = t3; t3 = INF_KEY;
            if (--occ == 0) {
                // rare exact refill: next 4 keys strictly greater than lastk
                t0 = t1 = t2 = t3 = INF_KEY;
#pragma unroll
                for (int r = 0; r < 16; r++) {
                    const uint32_t cbase = lb + ((r >> 2) << 8) + ((r & 3) << 1);
                    uint32_t klo = (pk[r] << 16) | cbase;
                    uint32_t khi = (pk[r] & 0xFFFF0000u) | (cbase + 1);
#pragma unroll
                    for (int h = 0; h < 2; h++) {
                        uint32_t k = h ? khi : klo;
                        if (k > lastk && k < t3) {
                            bool b0 = k < t0, b1 = k < t1, b2 = k < t2;
                            t3 = b2 ? t2 : k;
                            t2 = b2 ? (b1 ? t1 : k) : t2;
                            t1 = b1 ? (b0 ? t0 : k) : t1;
                            t0 = b0 ? k : t0;
                        }
                    }
                }
                occ = 4;
            }
        }
    }

    // ---- coalesced exact fp32 rescore: 4 lanes per candidate, 8 cands/rep ----
    const float* xb = x + (((size_t)(b << 10)) << 6);
    const float2* xip = (const float2*)(xb + ((size_t)n << 6));
    float2 xi2 = xip[lane];
    *(float2*)&sxi[w][lane * 2] = xi2;
    scand[w][lane] = (int)mycand;
    __syncwarp();
    const float4* xs4 = (const float4*)sxi[w];
    const int sub = lane & 3;          // position within quad
#pragma unroll
    for (int rep = 0; rep < 4; rep++) {
        const int ci = rep * 8 + (lane >> 2);
        const int cq = scand[w][ci];
        const float4* xc = (const float4*)(xb + ((size_t)cq << 6));
        float part = 0.f;
#pragma unroll
        for (int q = 0; q < 4; q++) {
            float4 cv = xc[q * 4 + sub];       // contiguous 64B per quad
            float4 xq = xs4[q * 4 + sub];
            part = fmaf(cv.x, xq.x, part);
            part = fmaf(cv.y, xq.y, part);
            part = fmaf(cv.z, xq.z, part);
            part = fmaf(cv.w, xq.w, part);
        }
        part += __shfl_xor_sync(0xffffffffu, part, 1);
        part += __shfl_xor_sync(0xffffffffu, part, 2);
        if (sub == 0) sdot[w][ci] = part;
    }
    __syncwarp();
    const int myc = scand[w][lane];
    float dv = fmaxf(fmaf(-2.0f, sdot[w][lane],
                          g_x2[(b << 10) + n] + g_x2[(b << 10) + myc]), 0.0f);
    int ci = myc;

    // ---- bitonic sort 32 lanes by (value, index) ascending ----
#pragma unroll
    for (int k = 2; k <= 32; k <<= 1) {
#pragma unroll
        for (int j = k >> 1; j > 0; j >>= 1) {
            float ov = __shfl_xor_sync(0xffffffffu, dv, j);
            int   oi = __shfl_xor_sync(0xffffffffu, ci, j);
            bool up = ((lane & k) == 0);
            bool lower = ((lane & j) == 0);
            bool otherLess = (ov < dv) || (ov == dv && oi < ci);
            bool take = (up == lower) ? otherLess : !otherLess;
            if (take) { dv = ov; ci = oi; }
        }
    }
    if (lane < KMAX) {
        int ke = g_keff[b];
        g_idx[warp * KMAX + lane] = (lane < ke) ? ci : 0;   // pad = first valid (0)
    }
}

// ---------------------------------------------------------------------------
// 5) per-point t = x@(W1a - W1b) + b1  and  u = x@W1b.  32 rows per block.
//    Blocks whose rows are all invalid exit (rows never read downstream).
// ---------------------------------------------------------------------------
__global__ void k_tu(const float* __restrict__ x, const float* __restrict__ W1,
                     const float* __restrict__ b1) {
    __shared__ float xs[32][64];
    __shared__ __align__(16) float w1s[64][128];
    const int tid = threadIdx.x;            // 256
    const int rowBase = blockIdx.x * 32;
    if ((rowBase & 1023) >= g_cnt[rowBase >> 10]) return;   // block-uniform

    for (int idx = tid; idx < 64 * 128; idx += 256) {
        int d = idx >> 7, c = idx & 127;
        float v;
        if (c < 64) v = W1[d * 64 + c] - W1[(64 + d) * 64 + c];
        else        v = W1[(64 + d) * 64 + (c - 64)];
        w1s[d][c] = v;
    }
    for (int idx = tid; idx < 32 * 64; idx += 256) {
        int r = idx >> 6, k = idx & 63;
        xs[r][k] = x[(size_t)(rowBase + r) * D + k];
    }
    __syncthreads();

    const int tx = tid & 15;
    const int ty = tid >> 4;
    float acc[2][8] = {};
    for (int k = 0; k < 64; k++) {
        float a0 = xs[ty * 2 + 0][k];
        float a1 = xs[ty * 2 + 1][k];
        float4 w0 = *reinterpret_cast<const float4*>(&w1s[k][tx * 8 + 0]);
        float4 w1v = *reinterpret_cast<const float4*>(&w1s[k][tx * 8 + 4]);
        float w[8] = {w0.x, w0.y, w0.z, w0.w, w1v.x, w1v.y, w1v.z, w1v.w};
#pragma unroll
        for (int j = 0; j < 8; j++) {
            acc[0][j] = fmaf(a0, w[j], acc[0][j]);
            acc[1][j] = fmaf(a1, w[j], acc[1][j]);
        }
    }
#pragma unroll
    for (int i = 0; i < 2; i++) {
        int row = rowBase + ty * 2 + i;
#pragma unroll
        for (int j = 0; j < 8; j++) {
            int c = tx * 8 + j;
            float v = acc[i][j] + (c < 64 ? b1[c] : 0.0f);
            g_tu[(size_t)row * 128 + c] = v;
        }
    }
}

// ---------------------------------------------------------------------------
// 6) fused via tf32 mma (4 rows/CTA, one row per warp).
//    Phase 1: gather u, GroupNorm+ReLU, cvt tf32 -> smem h[24x64].
//    Phase 2: m16n8k8 tf32 GEMM out[64 ch][24 edges], max over valid edge
//    cols, +b2, store.
// ---------------------------------------------------------------------------
#define HS_STRIDE 68
#define W2_STRIDE 72

__device__ __forceinline__ void mma_tf32(float* c, uint32_t a0, uint32_t a1,
                                         uint32_t a2, uint32_t a3,
                                         uint32_t b0v, uint32_t b1v) {
    asm volatile(
        "mma.sync.aligned.m16n8k8.row.col.f32.tf32.tf32.f32 "
        "{%0,%1,%2,%3}, {%4,%5,%6,%7}, {%8,%9}, {%0,%1,%2,%3};"
        : "+f"(c[0]), "+f"(c[1]), "+f"(c[2]), "+f"(c[3])
        : "r"(a0), "r"(a1), "r"(a2), "r"(a3), "r"(b0v), "r"(b1v));
}

__global__ void __launch_bounds__(128) k_fused_mma(
    const float* __restrict__ W2, const float* __restrict__ b2,
    const float* __restrict__ gamma, const float* __restrict__ beta,
    float* __restrict__ out) {
    __shared__ float W2s[64 * W2_STRIDE];      // A[m][k]=W2[k][m], stored [k][m]
    __shared__ float hs[4][24 * HS_STRIDE];    // per-warp h tile [edge][ch]

    const int tid = threadIdx.x;
    const int w = tid >> 5;
    const int lane = tid & 31;
    const int gID = lane >> 2;
    const int tig = lane & 3;
    const unsigned FULL = 0xffffffffu;

    // load W2 into smem as tf32 bits
    for (int idx = tid; idx < 64 * 64; idx += 128) {
        int k = idx >> 6, m = idx & 63;
        uint32_t tv;
        asm("cvt.rna.tf32.f32 %0, %1;" : "=r"(tv) : "f"(W2[idx]));
        W2s[k * W2_STRIDE + m] = __uint_as_float(tv);
    }
    __syncthreads();

    const int row = (blockIdx.x << 2) + w;
    const int b = row >> 10;
    const int n = row & 1023;
    float* hw = hs[w];

    if (n >= g_cnt[b]) {
        *(float2*)&out[(size_t)row * 64 + 2 * lane] = make_float2(0.f, 0.f);
        return;
    }

    // ---- phase 1: h = relu(groupnorm(t + u_j)) -> smem tf32 ----
    int myidx = (lane < KMAX) ? g_idx[row * KMAX + lane] : 0;
    const float2 t2 = *(const float2*)&g_tu[(size_t)row * 128 + 2 * lane];
    const float2 gm = *(const float2*)&gamma[2 * lane];
    const float2 bt = *(const float2*)&beta[2 * lane];
#pragma unroll
    for (int j = KMAX; j < 24; j++)
        *(float2*)&hw[j * HS_STRIDE + 2 * lane] = make_float2(0.f, 0.f);
#pragma unroll 4
    for (int j = 0; j < KMAX; j++) {
        int sid = __shfl_sync(FULL, myidx, j);
        const float2 u2 = *(const float2*)
            &g_tu[((size_t)((b << 10) + sid)) * 128 + 64 + 2 * lane];
        float h0 = t2.x + u2.x, h1 = t2.y + u2.y;
        float s = h0 + h1;
        s += __shfl_xor_sync(FULL, s, 1);
        const float mu = s * 0.25f;
        const float d0 = h0 - mu, d1 = h1 - mu;
        float vv = d0 * d0 + d1 * d1;
        vv += __shfl_xor_sync(FULL, vv, 1);
        const float rstd = rsqrtf(vv * 0.25f + 1e-5f);
        float hn0 = fmaxf(fmaf(d0 * rstd, gm.x, bt.x), 0.f);
        float hn1 = fmaxf(fmaf(d1 * rstd, gm.y, bt.y), 0.f);
        uint32_t p0, p1;
        asm("cvt.rna.tf32.f32 %0, %1;" : "=r"(p0) : "f"(hn0));
        asm("cvt.rna.tf32.f32 %0, %1;" : "=r"(p1) : "f"(hn1));
        hw[j * HS_STRIDE + 2 * lane]     = __uint_as_float(p0);
        hw[j * HS_STRIDE + 2 * lane + 1] = __uint_as_float(p1);
    }
    __syncwarp();

    // ---- phase 2: GEMM M=64 (out_ch), N=24 (edges), K=64 (in_ch) ----
    float c[4][3][4];
#pragma unroll
    for (int mt = 0; mt < 4; mt++)
#pragma unroll
        for (int nt = 0; nt < 3; nt++)
#pragma unroll
            for (int e = 0; e < 4; e++) c[mt][nt][e] = 0.f;

#pragma unroll
    for (int k0 = 0; k0 < 8; k0++) {
        const int kk = k0 * 8;
        uint32_t bf[3][2];
#pragma unroll
        for (int nt = 0; nt < 3; nt++) {
            bf[nt][0] = __float_as_uint(hw[(nt * 8 + gID) * HS_STRIDE + kk + tig]);
            bf[nt][1] = __float_as_uint(hw[(nt * 8 + gID) * HS_STRIDE + kk + tig + 4]);
        }
#pragma unroll
        for (int mt = 0; mt < 4; mt++) {
            const int mb = mt * 16 + gID;
            uint32_t a0 = __float_as_uint(W2s[(kk + tig) * W2_STRIDE + mb]);
            uint32_t a1 = __float_as_uint(W2s[(kk + tig) * W2_STRIDE + mb + 8]);
            uint32_t a2 = __float_as_uint(W2s[(kk + tig + 4) * W2_STRIDE + mb]);
            uint32_t a3 = __float_as_uint(W2s[(kk + tig + 4) * W2_STRIDE + mb + 8]);
#pragma unroll
            for (int nt = 0; nt < 3; nt++)
                mma_tf32(c[mt][nt], a0, a1, a2, a3, bf[nt][0], bf[nt][1]);
        }
    }

    // ---- epilogue: max over edge columns (exclude pad cols >= 20) ----
    const bool inc2 = (tig < 2);   // ntile 2 cols 16+2tig(,+1) < 20
#pragma unroll
    for (int mt = 0; mt < 4; mt++) {
        float m0v = fmaxf(fmaxf(c[mt][0][0], c[mt][0][1]),
                          fmaxf(c[mt][1][0], c[mt][1][1]));
        float m1v = fmaxf(fmaxf(c[mt][0][2], c[mt][0][3]),
                          fmaxf(c[mt][1][2], c[mt][1][3]));
        if (inc2) {
            m0v = fmaxf(m0v, fmaxf(c[mt][2][0], c[mt][2][1]));
            m1v = fmaxf(m1v, fmaxf(c[mt][2][2], c[mt][2][3]));
        }
        m0v = fmaxf(m0v, __shfl_xor_sync(FULL, m0v, 1));
        m0v = fmaxf(m0v, __shfl_xor_sync(FULL, m0v, 2));
        m1v = fmaxf(m1v, __shfl_xor_sync(FULL, m1v, 1));
        m1v = fmaxf(m1v, __shfl_xor_sync(FULL, m1v, 2));
        if (tig == 0) {
            const int ch0 = mt * 16 + gID;
            out[(size_t)row * 64 + ch0]     = m0v + b2[ch0];
            out[(size_t)row * 64 + ch0 + 8] = m1v + b2[ch0 + 8];
        }
    }
}

// ---------------------------------------------------------------------------
// launch
// ---------------------------------------------------------------------------
extern "C" void kernel_launch(void* const* d_in, const int* in_sizes, int n_in,
                              void* d_out, int out_size) {
    const float* x = (const float*)d_in[0];
    const void* mask = d_in[1];
    const float* W1 = (const float*)d_in[2];
    const float* b1 = (const float*)d_in[3];
    const float* gamma = (const float*)d_in[4];
    const float* beta = (const float*)d_in[5];
    const float* W2 = (const float*)d_in[6];
    const float* b2 = (const float*)d_in[7];
    float* out = (float*)d_out;

    k_x2c<<<65, 256>>>(x, mask);
    k_dist_mma<<<dim3(N / 128, N / 128, B), 256>>>();
    k_select<<<(B * N) / 4, 128>>>(x);
    k_tu<<<(B * N) / 32, 256>>>(x, W1, b1);
    k_fused_mma<<<(B * N) / 4, 128>>>(W2, b2, gamma, beta, out);
}